// round 12
// baseline (speedup 1.0000x reference)
#include <cuda_runtime.h>
#include <cuda_bf16.h>
#include <cstdint>

typedef __nv_bfloat16 bf16;

// Problem constants: B=4, S=4096, HID=2048, H=16, P=256, D=128, N=16
// Key-axis permutation: paged row index p2' = par*128 + dim.
#define NELEM 33554432u
#define MDIM 16384
#define NDIM 2048
#define NCH2 64           // 32 K-cols per chunk, hi+lo fused

__device__ bf16 g_qhi[NELEM];
__device__ bf16 g_qlo[NELEM];
__device__ bf16 g_khi[NELEM];
__device__ bf16 g_klo[NELEM];
__device__ bf16 g_vthi[NELEM];  // transposed: [page][d2:128][p2':256]
__device__ bf16 g_vtlo[NELEM];

// compact split layout: [rows][4096] = [hi(2048) | lo(2048)]
__device__ bf16 g_hbig[(size_t)MDIM * 4096];
__device__ bf16 g_cbig[(size_t)MDIM * 4096];
__device__ bf16 g_wq[(size_t)NDIM * 4096];
__device__ bf16 g_wk[(size_t)NDIM * 4096];
__device__ bf16 g_wv[(size_t)NDIM * 4096];
__device__ bf16 g_wo[(size_t)NDIM * 4096];

// ---------------------------------------------------------------------------
// helpers
// ---------------------------------------------------------------------------
__device__ __forceinline__ uint32_t smem_u32(const void* p) {
    uint32_t a;
    asm("{ .reg .u64 t; cvta.to.shared.u64 t, %1; cvt.u32.u64 %0, t; }"
        : "=r"(a) : "l"(p));
    return a;
}
__device__ __forceinline__ void cp16(uint32_t sa, const void* g) {
    asm volatile("cp.async.cg.shared.global [%0], [%1], 16;" :: "r"(sa), "l"(g));
}
#define CP_COMMIT() asm volatile("cp.async.commit_group;" ::: "memory")

__device__ __forceinline__ void ldsm4(uint32_t* r, uint32_t addr) {
    asm volatile("ldmatrix.sync.aligned.m8n8.x4.shared.b16 {%0,%1,%2,%3}, [%4];"
                 : "=r"(r[0]), "=r"(r[1]), "=r"(r[2]), "=r"(r[3]) : "r"(addr));
}
__device__ __forceinline__ void mma16816(float* c, const uint32_t* a,
                                         const uint32_t* b) {
    asm volatile(
        "mma.sync.aligned.m16n8k16.row.col.f32.bf16.bf16.f32 "
        "{%0,%1,%2,%3}, {%4,%5,%6,%7}, {%8,%9}, {%0,%1,%2,%3};"
        : "+f"(c[0]), "+f"(c[1]), "+f"(c[2]), "+f"(c[3])
        : "r"(a[0]), "r"(a[1]), "r"(a[2]), "r"(a[3]), "r"(b[0]), "r"(b[1]));
}
__device__ __forceinline__ uint32_t swz(uint32_t o) { return o ^ ((o >> 3) & 0x70); }
__device__ __forceinline__ uint32_t swz64(uint32_t o) { return o ^ ((o >> 3) & 0x30); }
__device__ __forceinline__ uint32_t pack2(bf16 a, bf16 b) {
    return (uint32_t)*(uint16_t*)&a | ((uint32_t)*(uint16_t*)&b << 16);
}
__device__ __forceinline__ uint32_t packhi(float a, float b) {
    return pack2(__float2bfloat16(a), __float2bfloat16(b));
}
__device__ __forceinline__ uint32_t packlo(float a, float b) {
    bf16 ha = __float2bfloat16(a), hb = __float2bfloat16(b);
    return pack2(__float2bfloat16(a - __bfloat162float(ha)),
                 __float2bfloat16(b - __bfloat162float(hb)));
}

// ---------------------------------------------------------------------------
// fp32 -> compact split-bf16 [hi | lo]
// ---------------------------------------------------------------------------
__device__ __forceinline__ void split_one(const float* __restrict__ src,
                                          bf16* __restrict__ dst, size_t t) {
    size_t row = t >> 9;
    int col = (int)(t & 511) << 2;
    float4 x = *(const float4*)(src + row * 2048 + col);
    bf16 h[4], l[4];
    float xs[4] = {x.x, x.y, x.z, x.w};
#pragma unroll
    for (int i = 0; i < 4; i++) {
        h[i] = __float2bfloat16(xs[i]);
        l[i] = __float2bfloat16(xs[i] - __bfloat162float(h[i]));
    }
    bf16* d0 = dst + row * 4096 + col;
    ((uint32_t*)d0)[0] = pack2(h[0], h[1]);
    ((uint32_t*)d0)[1] = pack2(h[2], h[3]);
    ((uint32_t*)(d0 + 2048))[0] = pack2(l[0], l[1]);
    ((uint32_t*)(d0 + 2048))[1] = pack2(l[2], l[3]);
}

__global__ __launch_bounds__(256)
void make_split(const float* __restrict__ src, bf16* __restrict__ dst) {
    split_one(src, dst, (size_t)blockIdx.x * 256 + threadIdx.x);
}

__global__ __launch_bounds__(256)
void make_split4(const float* __restrict__ s0, bf16* __restrict__ d0,
                 const float* __restrict__ s1, bf16* __restrict__ d1,
                 const float* __restrict__ s2, bf16* __restrict__ d2,
                 const float* __restrict__ s3, bf16* __restrict__ d3) {
    const float* s = blockIdx.y == 0 ? s0 : blockIdx.y == 1 ? s1
                     : blockIdx.y == 2 ? s2 : s3;
    bf16* d = blockIdx.y == 0 ? d0 : blockIdx.y == 1 ? d1
              : blockIdx.y == 2 ? d2 : d3;
    split_one(s, d, (size_t)blockIdx.x * 256 + threadIdx.x);
}

// ---------------------------------------------------------------------------
// GEMM mainloop v2: 128m x 128n block, 2 CTAs/SM. 64 chunks of 32 K-cols,
// each chunk's 128B smem row = [hi 64B | lo 64B]. All 3 split terms computed
// per chunk with fragment reuse (aH·bH, aH·bL, aL·bH). 3-stage ring.
// ---------------------------------------------------------------------------
#define NSTG 3
#define STG_BYTES 32768   // A 16KB + W 16KB
#define GEMM_SMEM (NSTG * STG_BYTES)

__device__ __forceinline__ void load_chunk(
    const bf16* __restrict__ A, const bf16* __restrict__ W,
    uint32_t stg, int bm, int bn, int chunk, int tid) {
#pragma unroll
    for (int j = 0; j < 8; j++) {
        int idx = j * 256 + tid;          // 0..2047
        bool isB = idx >= 1024;
        int rem = idx & 1023;
        int r = rem >> 3;                 // 0..127
        int seg = rem & 7;                // 16B segment in row
        int prec = seg >> 2;              // 0 hi, 1 lo
        const bf16* base = isB ? W + (size_t)(bn + r) * 4096
                               : A + (size_t)(bm + r) * 4096;
        const bf16* src = base + prec * 2048 + chunk * 32 + (seg & 3) * 8;
        uint32_t off = swz((uint32_t)(r * 128 + seg * 16));
        cp16(stg + (isB ? 16384 : 0) + off, src);
    }
    CP_COMMIT();
}

__device__ __forceinline__ void gemm_mainloop(
    const bf16* __restrict__ A, const bf16* __restrict__ W,
    uint32_t data, int bm, int bn, float (&acc)[4][4][4],
    int tid, int wid, int lane) {
    const int m_base = (wid & 1) * 64;
    const int n_base = (wid >> 1) * 32;

    load_chunk(A, W, data, bm, bn, 0, tid);
    load_chunk(A, W, data + STG_BYTES, bm, bn, 1, tid);

    const int raL = lane & 15;
    const int akh = lane >> 4;
    const int rbL = (lane & 7) + ((lane & 16) >> 1);
    const int bkh = (lane >> 3) & 1;

    int stg_i = 0;
    for (int i = 0; i < NCH2; i++) {
        if (i < NCH2 - 1)
            asm volatile("cp.async.wait_group 1;" ::: "memory");
        else
            asm volatile("cp.async.wait_group 0;" ::: "memory");
        __syncthreads();

        int nc = i + 2;
        int stg_n = stg_i + 2; if (stg_n >= NSTG) stg_n -= NSTG;
        if (nc < NCH2)
            load_chunk(A, W, data + stg_n * STG_BYTES, bm, bn, nc, tid);

        uint32_t sA = data + stg_i * STG_BYTES;
        uint32_t sW = sA + 16384;

#pragma unroll
        for (int ks = 0; ks < 2; ks++) {
            // hi k16 at ck-index ks*2, lo k16 at (ks+2)*2
            uint32_t a[4][4], bH[2][4], bL[2][4];
#pragma unroll
            for (int mt = 0; mt < 4; mt++) {
                int ra = m_base + mt * 16 + raL;
                uint32_t ck = (uint32_t)(ks * 2 + akh) ^ (uint32_t)(ra & 7);
                ldsm4(a[mt], sA + (uint32_t)(ra * 128) + (ck << 4));
            }
#pragma unroll
            for (int nt2 = 0; nt2 < 2; nt2++) {
                int rb = n_base + nt2 * 16 + rbL;
                uint32_t ckh = (uint32_t)(ks * 2 + bkh) ^ (uint32_t)(rb & 7);
                ldsm4(bH[nt2], sW + (uint32_t)(rb * 128) + (ckh << 4));
            }
#pragma unroll
            for (int mt = 0; mt < 4; mt++)
#pragma unroll
                for (int nt = 0; nt < 4; nt++)
                    mma16816(acc[mt][nt], a[mt], &bH[nt >> 1][(nt & 1) * 2]);
#pragma unroll
            for (int nt2 = 0; nt2 < 2; nt2++) {
                int rb = n_base + nt2 * 16 + rbL;
                uint32_t ckl = (uint32_t)((ks + 2) * 2 + bkh) ^ (uint32_t)(rb & 7);
                ldsm4(bL[nt2], sW + (uint32_t)(rb * 128) + (ckl << 4));
            }
#pragma unroll
            for (int mt = 0; mt < 4; mt++)
#pragma unroll
                for (int nt = 0; nt < 4; nt++)
                    mma16816(acc[mt][nt], a[mt], &bL[nt >> 1][(nt & 1) * 2]);
            // reload a as A-lo, multiply with bH
#pragma unroll
            for (int mt = 0; mt < 4; mt++) {
                int ra = m_base + mt * 16 + raL;
                uint32_t ck = (uint32_t)((ks + 2) * 2 + akh) ^ (uint32_t)(ra & 7);
                ldsm4(a[mt], sA + (uint32_t)(ra * 128) + (ck << 4));
            }
#pragma unroll
            for (int mt = 0; mt < 4; mt++)
#pragma unroll
                for (int nt = 0; nt < 4; nt++)
                    mma16816(acc[mt][nt], a[mt], &bH[nt >> 1][(nt & 1) * 2]);
        }
        if (++stg_i == NSTG) stg_i = 0;
    }
    __syncthreads();
}

// ---------------------------------------------------------------------------
// Merged QKV GEMM. grid (48, 128): wsel = x>>4, bn=(x&15)*128 (one head).
// ---------------------------------------------------------------------------
__global__ __launch_bounds__(256, 2)
void gemm_qkv(const bf16* __restrict__ A,
              const bf16* __restrict__ W0, const bf16* __restrict__ W1,
              const bf16* __restrict__ W2,
              const float* __restrict__ b0, const float* __restrict__ b1,
              const float* __restrict__ b2,
              bf16* __restrict__ qhi, bf16* __restrict__ qlo,
              bf16* __restrict__ khi, bf16* __restrict__ klo,
              bf16* __restrict__ vthi, bf16* __restrict__ vtlo) {
    extern __shared__ char dsm[];
    const uint32_t data = smem_u32(dsm);
    const int tid = threadIdx.x, wid = tid >> 5, lane = tid & 31;
    const int wsel = blockIdx.x >> 4;
    const int bn = (blockIdx.x & 15) << 7;
    const int bm = blockIdx.y << 7;
    const bf16* W = wsel == 0 ? W0 : wsel == 1 ? W1 : W2;
    const float* bias = wsel == 0 ? b0 : wsel == 1 ? b1 : b2;

    float acc[4][4][4];
#pragma unroll
    for (int mt = 0; mt < 4; mt++)
#pragma unroll
        for (int nt = 0; nt < 4; nt++)
#pragma unroll
            for (int r = 0; r < 4; r++) acc[mt][nt][r] = 0.f;

    gemm_mainloop(A, W, data, bm, bn, acc, tid, wid, lane);

    const int m_base = (wid & 1) * 64;
    const int n_base = (wid >> 1) * 32;

#pragma unroll
    for (int mt = 0; mt < 4; mt++)
#pragma unroll
        for (int nt = 0; nt < 4; nt++) {
            int col = bn + n_base + nt * 8 + (lane & 3) * 2;
            float bb0 = bias[col], bb1 = bias[col + 1];
            acc[mt][nt][0] += bb0; acc[mt][nt][1] += bb1;
            acc[mt][nt][2] += bb0; acc[mt][nt][3] += bb1;
        }

    const int b = bm >> 12, s0 = bm & 4095;
    const int page = s0 >> 8, par = (s0 >> 7) & 1;
    const int head = bn >> 7;
    size_t pb = ((size_t)((b * 16 + head) * 16 + page)) << 15;

    if (wsel < 2) {
        bf16* dhi = wsel ? khi : qhi;
        bf16* dlo = wsel ? klo : qlo;
        float* smf = (float*)dsm;  // [c:128][r:132]
#pragma unroll
        for (int mt = 0; mt < 4; mt++) {
            int r = m_base + mt * 16 + (lane >> 2);
#pragma unroll
            for (int nt = 0; nt < 4; nt++) {
                int c = n_base + nt * 8 + (lane & 3) * 2;
                smf[c * 132 + r] = acc[mt][nt][0];
                smf[(c + 1) * 132 + r] = acc[mt][nt][1];
                smf[c * 132 + r + 8] = acc[mt][nt][2];
                smf[(c + 1) * 132 + r + 8] = acc[mt][nt][3];
            }
        }
        __syncthreads();
        for (int cc = wid; cc < 128; cc += 8) {
            float4 v = *(const float4*)&smf[cc * 132 + lane * 4];
            size_t off = pb + (size_t)(par * 128 + cc) * 128 + lane * 4;
            *(uint2*)(dhi + off) = make_uint2(packhi(v.x, v.y), packhi(v.z, v.w));
            *(uint2*)(dlo + off) = make_uint2(packlo(v.x, v.y), packlo(v.z, v.w));
        }
    } else {
#pragma unroll
        for (int nt = 0; nt < 4; nt++) {
            int cw = n_base + nt * 8 + (lane & 3) * 2;
#pragma unroll
            for (int mt = 0; mt < 4; mt++) {
                int r0 = m_base + mt * 16 + (lane >> 2);
#pragma unroll
                for (int q = 0; q < 2; q++) {
                    int r = r0 + q * 8;
                    float v0 = acc[mt][nt][q * 2], v1 = acc[mt][nt][q * 2 + 1];
                    size_t off = pb + (size_t)r * 256 + par * 128 + cw;
                    *(uint32_t*)(vthi + off) = packhi(v0, v1);
                    *(uint32_t*)(vtlo + off) = packlo(v0, v1);
                }
            }
        }
    }
}

// ---------------------------------------------------------------------------
// Wo GEMM: plain fp32 output
// ---------------------------------------------------------------------------
__global__ __launch_bounds__(256, 2)
void gemm_wo(const bf16* __restrict__ A, const bf16* __restrict__ W,
             const float* __restrict__ bias, float* __restrict__ C) {
    extern __shared__ char dsm[];
    const uint32_t data = smem_u32(dsm);
    const int tid = threadIdx.x, wid = tid >> 5, lane = tid & 31;
    const int bn = blockIdx.x << 7, bm = blockIdx.y << 7;

    float acc[4][4][4];
#pragma unroll
    for (int mt = 0; mt < 4; mt++)
#pragma unroll
        for (int nt = 0; nt < 4; nt++)
#pragma unroll
            for (int r = 0; r < 4; r++) acc[mt][nt][r] = 0.f;

    gemm_mainloop(A, W, data, bm, bn, acc, tid, wid, lane);

    const int m_base = (wid & 1) * 64;
    const int n_base = (wid >> 1) * 32;
#pragma unroll
    for (int mt = 0; mt < 4; mt++) {
        int r0 = bm + m_base + mt * 16 + (lane >> 2);
#pragma unroll
        for (int nt = 0; nt < 4; nt++) {
            int col = bn + n_base + nt * 8 + (lane & 3) * 2;
            float bb0 = bias[col], bb1 = bias[col + 1];
            float* p0 = C + (size_t)r0 * NDIM + col;
            float* p1 = p0 + (size_t)8 * NDIM;
            *(float2*)p0 = make_float2(acc[mt][nt][0] + bb0, acc[mt][nt][1] + bb1);
            *(float2*)p1 = make_float2(acc[mt][nt][2] + bb0, acc[mt][nt][3] + bb1);
        }
    }
}

// ---------------------------------------------------------------------------
// attn4: FA2-style register-resident online softmax + fragment-reuse 3-term.
// 128 threads, 4 warps x 16 q-rows = 64 rows/block. 8 K/V tiles of 32.
// smem: Q 32K @0, slot0 @32K (K 16K + V 16K), slot1 @64K. 2 CTAs/SM.
// ---------------------------------------------------------------------------
#define A4_Q 0u
#define A4_S0 32768u
#define A4_S1 65536u
#define A4_SMEM 98304

__device__ __forceinline__ void a4_load_tile(
    uint32_t slot, const bf16* __restrict__ khi, const bf16* __restrict__ klo,
    const bf16* __restrict__ vthi, const bf16* __restrict__ vtlo,
    size_t pagebase, int kt, int tid) {
#pragma unroll
    for (int j = 0; j < 8; j++) {
        int idx = j * 128 + tid;
        int prec = idx >> 9, rem = idx & 511;
        int r = rem >> 4, sub = rem & 15, kc = sub >> 3, c16 = sub & 7;
        cp16(slot + prec * 8192 + kc * 4096 + swz((uint32_t)(r * 128 + c16 * 16)),
             (prec ? klo : khi) + pagebase + (size_t)(kt * 32 + r) * 128 +
                 kc * 64 + c16 * 8);
    }
#pragma unroll
    for (int j = 0; j < 8; j++) {
        int idx = j * 128 + tid;
        int prec = idx >> 9, rem = idx & 511;
        int r = rem >> 2, c16 = rem & 3;
        cp16(slot + 16384 + prec * 8192 + swz64((uint32_t)(r * 64 + c16 * 16)),
             (prec ? vtlo : vthi) + pagebase + (size_t)r * 256 + kt * 32 + c16 * 8);
    }
    CP_COMMIT();
}

__global__ __launch_bounds__(128, 2)
void attn4(const bf16* __restrict__ qhi, const bf16* __restrict__ qlo,
           const bf16* __restrict__ khi, const bf16* __restrict__ klo,
           const bf16* __restrict__ vthi, const bf16* __restrict__ vtlo,
           bf16* __restrict__ cbig) {
    extern __shared__ char smraw[];
    const uint32_t sb = smem_u32(smraw);

    const float SCALE = 0.08838834764831843f;
    const int qt = blockIdx.x, h2 = blockIdx.y, x2 = blockIdx.z;
    const int tid = threadIdx.x, wid = tid >> 5, lane = tid & 31;
    const size_t pagebase = ((size_t)(x2 * 16 + h2)) << 15;

    const int raL = lane & 15, akh = lane >> 4;
    const int rbL = (lane & 7) + ((lane & 16) >> 1), bkh = (lane >> 3) & 1;

#pragma unroll
    for (int j = 0; j < 16; j++) {
        int idx = j * 128 + tid;
        int prec = idx >> 10, rem = idx & 1023;
        int r = rem >> 4, kc = (rem >> 3) & 1, c16 = rem & 7;
        cp16(sb + A4_Q + prec * 16384 + kc * 8192 + swz((uint32_t)(r * 128 + c16 * 16)),
             (prec ? qlo : qhi) + pagebase + (size_t)(qt * 64 + r) * 128 +
                 kc * 64 + c16 * 8);
    }
    a4_load_tile(sb + A4_S0, khi, klo, vthi, vtlo, pagebase, 0, tid);
    a4_load_tile(sb + A4_S1, khi, klo, vthi, vtlo, pagebase, 1, tid);

    float out[16][4];
#pragma unroll
    for (int j = 0; j < 16; j++)
#pragma unroll
        for (int r = 0; r < 4; r++) out[j][r] = 0.f;
    float m0 = -3.4e38f, m1 = -3.4e38f, l0 = 0.f, l1 = 0.f;

#pragma unroll 1
    for (int kt = 0; kt < 8; kt++) {
        if (kt < 7) asm volatile("cp.async.wait_group 1;" ::: "memory");
        else        asm volatile("cp.async.wait_group 0;" ::: "memory");
        __syncthreads();

        uint32_t slot = sb + ((kt & 1) ? A4_S1 : A4_S0);

        // ---- S = Q K^T, fused 3-term with fragment reuse ----
        float sf[4][4];
#pragma unroll
        for (int j = 0; j < 4; j++)
#pragma unroll
            for (int r = 0; r < 4; r++) sf[j][r] = 0.f;

#pragma unroll
        for (int step = 0; step < 8; step++) {
            int kc = step >> 2, inner = step & 3;
            int ra = wid * 16 + raL;
            uint32_t ck = (uint32_t)(inner * 2 + akh) ^ (uint32_t)(ra & 7);
            uint32_t a[4], bH[2][4], bL[2][4];
            ldsm4(a, sb + A4_Q + kc * 8192 + (uint32_t)(ra * 128) + (ck << 4));
#pragma unroll
            for (int nt2 = 0; nt2 < 2; nt2++) {
                int rb = nt2 * 16 + rbL;
                uint32_t cb = (uint32_t)(inner * 2 + bkh) ^ (uint32_t)(rb & 7);
                ldsm4(bH[nt2], slot + kc * 4096 + (uint32_t)(rb * 128) + (cb << 4));
            }
#pragma unroll
            for (int nt = 0; nt < 4; nt++)
                mma16816(sf[nt], a, &bH[nt >> 1][(nt & 1) * 2]);
#pragma unroll
            for (int nt2 = 0; nt2 < 2; nt2++) {
                int rb = nt2 * 16 + rbL;
                uint32_t cb = (uint32_t)(inner * 2 + bkh) ^ (uint32_t)(rb & 7);
                ldsm4(bL[nt2], slot + 8192 + kc * 4096 + (uint32_t)(rb * 128) + (cb << 4));
            }
#pragma unroll
            for (int nt = 0; nt < 4; nt++)
                mma16816(sf[nt], a, &bL[nt >> 1][(nt & 1) * 2]);
            // Q-lo * K-hi
            ldsm4(a, sb + A4_Q + 16384 + kc * 8192 + (uint32_t)(ra * 128) + (ck << 4));
#pragma unroll
            for (int nt = 0; nt < 4; nt++)
                mma16816(sf[nt], a, &bH[nt >> 1][(nt & 1) * 2]);
        }

        // ---- online softmax update ----
        float tm0 = -3.4e38f, tm1 = -3.4e38f;
#pragma unroll
        for (int j = 0; j < 4; j++) {
#pragma unroll
            for (int r = 0; r < 4; r++) sf[j][r] *= SCALE;
            tm0 = fmaxf(tm0, fmaxf(sf[j][0], sf[j][1]));
            tm1 = fmaxf(tm1, fmaxf(sf[j][2], sf[j][3]));
        }
        tm0 = fmaxf(tm0, __shfl_xor_sync(0xffffffffu, tm0, 1));
        tm0 = fmaxf(tm0, __shfl_xor_sync(0xffffffffu, tm0, 2));
        tm1 = fmaxf(tm1, __shfl_xor_sync(0xffffffffu, tm1, 1));
        tm1 = fmaxf(tm1, __shfl_xor_sync(0xffffffffu, tm1, 2));
        float mn0 = fmaxf(m0, tm0), mn1 = fmaxf(m1, tm1);
        float f0 = __expf(m0 - mn0), f1 = __expf(m1 - mn1);
        m0 = mn0; m1 = mn1;

        float ps0 = 0.f, ps1 = 0.f;
#pragma unroll
        for (int j = 0; j < 4; j++) {
            sf[j][0] = __expf(sf[j][0] - mn0);
            sf[j][1] = __expf(sf[j][1] - mn0);
            sf[j][2] = __expf(sf[j][2] - mn1);
            sf[j][3] = __expf(sf[j][3] - mn1);
            ps0 += sf[j][0] + sf[j][1];
            ps1 += sf[j][2] + sf[j][3];
        }
        ps0 += __shfl_xor_sync(0xffffffffu, ps0, 1);
        ps0 += __shfl_xor_sync(0xffffffffu, ps0, 2);
        ps1 += __shfl_xor_sync(0xffffffffu, ps1, 1);
        ps1 += __shfl_xor_sync(0xffffffffu, ps1, 2);
        l0 = l0 * f0 + ps0;
        l1 = l1 * f1 + ps1;
#pragma unroll
        for (int j = 0; j < 16; j++) {
            out[j][0] *= f0; out[j][1] *= f0;
            out[j][2] *= f1; out[j][3] *= f1;
        }

        // ---- P fragments ----
        uint32_t phi[2][4], plo[2][4];
#pragma unroll
        for (int q = 0; q < 2; q++) {
            phi[q][0] = packhi(sf[2 * q][0], sf[2 * q][1]);
            phi[q][1] = packhi(sf[2 * q][2], sf[2 * q][3]);
            phi[q][2] = packhi(sf[2 * q + 1][0], sf[2 * q + 1][1]);
            phi[q][3] = packhi(sf[2 * q + 1][2], sf[2 * q + 1][3]);
            plo[q][0] = packlo(sf[2 * q][0], sf[2 * q][1]);
            plo[q][1] = packlo(sf[2 * q][2], sf[2 * q][3]);
            plo[q][2] = packlo(sf[2 * q + 1][0], sf[2 * q + 1][1]);
            plo[q][3] = packlo(sf[2 * q + 1][2], sf[2 * q + 1][3]);
        }

        // ---- out += P V, fused 3-term with Vhi fragment reuse ----
        uint32_t Vb = slot + 16384;
#pragma unroll
        for (int ks = 0; ks < 2; ks++) {
#pragma unroll
            for (int nt2 = 0; nt2 < 8; nt2++) {
                int rb = nt2 * 16 + rbL;
                uint32_t u = (uint32_t)(ks * 2 + bkh) ^ (uint32_t)((rb & 6) >> 1);
                uint32_t bv[4];
                ldsm4(bv, Vb + (uint32_t)(rb * 64) + (u << 4));
                mma16816(out[nt2 * 2], phi[ks], &bv[0]);
                mma16816(out[nt2 * 2 + 1], phi[ks], &bv[2]);
                mma16816(out[nt2 * 2], plo[ks], &bv[0]);
                mma16816(out[nt2 * 2 + 1], plo[ks], &bv[2]);
                ldsm4(bv, Vb + 8192 + (uint32_t)(rb * 64) + (u << 4));
                mma16816(out[nt2 * 2], phi[ks], &bv[0]);
                mma16816(out[nt2 * 2 + 1], phi[ks], &bv[2]);
            }
        }
        __syncthreads();

        if (kt + 2 < 8)
            a4_load_tile(sb + ((kt & 1) ? A4_S1 : A4_S0), khi, klo, vthi, vtlo,
                         pagebase, kt + 2, tid);
    }

    // ---- epilogue ----
    const int b = x2 >> 4, head = x2 & 15;
    float il0 = 1.f / l0, il1 = 1.f / l1;
    int rg0 = qt * 64 + wid * 16 + (lane >> 2);
#pragma unroll
    for (int rr = 0; rr < 2; rr++) {
        int r = rg0 + rr * 8;
        int p2 = 2 * (r & 127) + (r >> 7);
        float il = rr ? il1 : il0;
        bf16* drow = cbig + (size_t)(b * 4096 + head * 256 + p2) * 4096;
#pragma unroll
        for (int j = 0; j < 16; j++) {
            int colb = h2 * 128 + j * 8 + (lane & 3) * 2;
            float v0 = out[j][rr * 2] * il, v1 = out[j][rr * 2 + 1] * il;
            *(uint32_t*)(drow + colb) = packhi(v0, v1);
            *(uint32_t*)(drow + 2048 + colb) = packlo(v0, v1);
        }
    }
}

// ---------------------------------------------------------------------------
extern "C" void kernel_launch(void* const* d_in, const int* in_sizes, int n_in,
                              void* d_out, int out_size) {
    const float* hidden = (const float*)d_in[0];
    const float* Wq = (const float*)d_in[1];
    const float* bq = (const float*)d_in[2];
    const float* Wk = (const float*)d_in[3];
    const float* bk = (const float*)d_in[4];
    const float* Wv = (const float*)d_in[5];
    const float* bv = (const float*)d_in[6];
    const float* Wo = (const float*)d_in[7];
    const float* bo = (const float*)d_in[8];
    float* out = (float*)d_out;

    bf16 *hbig, *cbig, *wq, *wk, *wv, *wo;
    bf16 *qhi, *qlo, *khi, *klo, *vthi, *vtlo;
    cudaGetSymbolAddress((void**)&hbig, g_hbig);
    cudaGetSymbolAddress((void**)&cbig, g_cbig);
    cudaGetSymbolAddress((void**)&wq, g_wq);
    cudaGetSymbolAddress((void**)&wk, g_wk);
    cudaGetSymbolAddress((void**)&wv, g_wv);
    cudaGetSymbolAddress((void**)&wo, g_wo);
    cudaGetSymbolAddress((void**)&qhi, g_qhi);
    cudaGetSymbolAddress((void**)&qlo, g_qlo);
    cudaGetSymbolAddress((void**)&khi, g_khi);
    cudaGetSymbolAddress((void**)&klo, g_klo);
    cudaGetSymbolAddress((void**)&vthi, g_vthi);
    cudaGetSymbolAddress((void**)&vtlo, g_vtlo);

    cudaFuncSetAttribute(gemm_qkv, cudaFuncAttributeMaxDynamicSharedMemorySize,
                         GEMM_SMEM);
    cudaFuncSetAttribute(gemm_wo, cudaFuncAttributeMaxDynamicSharedMemorySize,
                         GEMM_SMEM);
    cudaFuncSetAttribute(attn4, cudaFuncAttributeMaxDynamicSharedMemorySize,
                         A4_SMEM);

    make_split4<<<dim3(4096, 4), 256>>>(Wq, wq, Wk, wk, Wv, wv, Wo, wo);
    make_split<<<32768, 256>>>(hidden, hbig);

    gemm_qkv<<<dim3(48, 128), 256, GEMM_SMEM>>>(
        hbig, wq, wk, wv, bq, bk, bv, qhi, qlo, khi, klo, vthi, vtlo);
    attn4<<<dim3(4, 16, 64), 128, A4_SMEM>>>(qhi, qlo, khi, klo, vthi, vtlo, cbig);
    gemm_wo<<<dim3(16, 128), 256, GEMM_SMEM>>>(cbig, wo, bo, out);
}

// round 13
// speedup vs baseline: 1.0545x; 1.0545x over previous
#include <cuda_runtime.h>
#include <cuda_bf16.h>
#include <cstdint>

typedef __nv_bfloat16 bf16;

// Problem constants: B=4, S=4096, HID=2048, H=16, P=256, D=128, N=16
// Key-axis permutation: paged row index p2' = par*128 + dim.
#define NELEM 33554432u
#define NCHUNK 96
#define MDIM 16384
#define NDIM 2048

__device__ bf16 g_qhi[NELEM];
__device__ bf16 g_qlo[NELEM];
__device__ bf16 g_khi[NELEM];
__device__ bf16 g_klo[NELEM];
__device__ bf16 g_vthi[NELEM];  // transposed: [page][d2:128][p2':256]
__device__ bf16 g_vtlo[NELEM];

// compact split layout: [rows][4096] = [hi(2048) | lo(2048)]
__device__ bf16 g_hbig[(size_t)MDIM * 4096];
__device__ bf16 g_cbig[(size_t)MDIM * 4096];
__device__ bf16 g_wq[(size_t)NDIM * 4096];
__device__ bf16 g_wk[(size_t)NDIM * 4096];
__device__ bf16 g_wv[(size_t)NDIM * 4096];
__device__ bf16 g_wo[(size_t)NDIM * 4096];

// ---------------------------------------------------------------------------
// helpers
// ---------------------------------------------------------------------------
__device__ __forceinline__ uint32_t smem_u32(const void* p) {
    uint32_t a;
    asm("{ .reg .u64 t; cvta.to.shared.u64 t, %1; cvt.u32.u64 %0, t; }"
        : "=r"(a) : "l"(p));
    return a;
}
__device__ __forceinline__ void cp16(uint32_t sa, const void* g) {
    asm volatile("cp.async.cg.shared.global [%0], [%1], 16;" :: "r"(sa), "l"(g));
}
#define CP_COMMIT() asm volatile("cp.async.commit_group;" ::: "memory")

__device__ __forceinline__ void ldsm4(uint32_t* r, uint32_t addr) {
    asm volatile("ldmatrix.sync.aligned.m8n8.x4.shared.b16 {%0,%1,%2,%3}, [%4];"
                 : "=r"(r[0]), "=r"(r[1]), "=r"(r[2]), "=r"(r[3]) : "r"(addr));
}
__device__ __forceinline__ void mma16816(float* c, const uint32_t* a,
                                         const uint32_t* b) {
    asm volatile(
        "mma.sync.aligned.m16n8k16.row.col.f32.bf16.bf16.f32 "
        "{%0,%1,%2,%3}, {%4,%5,%6,%7}, {%8,%9}, {%0,%1,%2,%3};"
        : "+f"(c[0]), "+f"(c[1]), "+f"(c[2]), "+f"(c[3])
        : "r"(a[0]), "r"(a[1]), "r"(a[2]), "r"(a[3]), "r"(b[0]), "r"(b[1]));
}
__device__ __forceinline__ uint32_t swz(uint32_t o) { return o ^ ((o >> 3) & 0x70); }
__device__ __forceinline__ uint32_t swz64(uint32_t o) { return o ^ ((o >> 3) & 0x30); }
__device__ __forceinline__ uint32_t pack2(bf16 a, bf16 b) {
    return (uint32_t)*(uint16_t*)&a | ((uint32_t)*(uint16_t*)&b << 16);
}
__device__ __forceinline__ uint32_t packhi(float a, float b) {
    return pack2(__float2bfloat16(a), __float2bfloat16(b));
}
__device__ __forceinline__ uint32_t packlo(float a, float b) {
    bf16 ha = __float2bfloat16(a), hb = __float2bfloat16(b);
    return pack2(__float2bfloat16(a - __bfloat162float(ha)),
                 __float2bfloat16(b - __bfloat162float(hb)));
}

// ---------------------------------------------------------------------------
// fp32 -> compact split-bf16 [hi | lo]
// ---------------------------------------------------------------------------
__device__ __forceinline__ void split_one(const float* __restrict__ src,
                                          bf16* __restrict__ dst, size_t t) {
    size_t row = t >> 9;
    int col = (int)(t & 511) << 2;
    float4 x = *(const float4*)(src + row * 2048 + col);
    bf16 h[4], l[4];
    float xs[4] = {x.x, x.y, x.z, x.w};
#pragma unroll
    for (int i = 0; i < 4; i++) {
        h[i] = __float2bfloat16(xs[i]);
        l[i] = __float2bfloat16(xs[i] - __bfloat162float(h[i]));
    }
    bf16* d0 = dst + row * 4096 + col;
    ((uint32_t*)d0)[0] = pack2(h[0], h[1]);
    ((uint32_t*)d0)[1] = pack2(h[2], h[3]);
    ((uint32_t*)(d0 + 2048))[0] = pack2(l[0], l[1]);
    ((uint32_t*)(d0 + 2048))[1] = pack2(l[2], l[3]);
}

__global__ __launch_bounds__(256)
void make_split(const float* __restrict__ src, bf16* __restrict__ dst) {
    split_one(src, dst, (size_t)blockIdx.x * 256 + threadIdx.x);
}

__global__ __launch_bounds__(256)
void make_split4(const float* __restrict__ s0, bf16* __restrict__ d0,
                 const float* __restrict__ s1, bf16* __restrict__ d1,
                 const float* __restrict__ s2, bf16* __restrict__ d2,
                 const float* __restrict__ s3, bf16* __restrict__ d3) {
    const float* s = blockIdx.y == 0 ? s0 : blockIdx.y == 1 ? s1
                     : blockIdx.y == 2 ? s2 : s3;
    bf16* d = blockIdx.y == 0 ? d0 : blockIdx.y == 1 ? d1
              : blockIdx.y == 2 ? d2 : d3;
    split_one(s, d, (size_t)blockIdx.x * 256 + threadIdx.x);
}

// ---------------------------------------------------------------------------
// GEMM mainloop (R11 formulation): 128m x 128n block, 2 CTAs/SM, 96 chunks
// of 64 K-cols with chunk->source remap into compact [hi|lo] operands:
//   chunk i: A col = (i<32 ? i : i-32)*64,  W col = (i<64 ? i : i-64)*64
// 3-stage cp.async ring, single sync per chunk. 8 warps as 2m x 4n (64x32).
// ---------------------------------------------------------------------------
#define NSTG 3
#define STG_BYTES 32768   // A 16KB + B 16KB
#define GEMM_SMEM (NSTG * STG_BYTES)

__device__ __forceinline__ void load_chunk(
    const bf16* __restrict__ A, const bf16* __restrict__ W,
    uint32_t stg, int bm, int bn, int chunk, int tid) {
    int acol = chunk < 32 ? chunk : chunk - 32;
    int wcol = chunk < 64 ? chunk : chunk - 64;
#pragma unroll
    for (int j = 0; j < 8; j++) {
        int idx = j * 256 + tid;
        bool isB = idx >= 1024;
        int r = (idx & 1023) >> 3;
        int c16 = idx & 7;
        const bf16* src = isB
            ? W + (size_t)(bn + r) * 4096 + wcol * 64 + c16 * 8
            : A + (size_t)(bm + r) * 4096 + acol * 64 + c16 * 8;
        uint32_t off = swz((uint32_t)(r * 128 + c16 * 16));
        cp16(stg + (isB ? 16384 : 0) + off, src);
    }
    CP_COMMIT();
}

__device__ __forceinline__ void gemm_mainloop(
    const bf16* __restrict__ A, const bf16* __restrict__ W,
    uint32_t data, int bm, int bn, float (&acc)[4][4][4],
    int tid, int wid, int lane) {
    const int m_base = (wid & 1) * 64;
    const int n_base = (wid >> 1) * 32;

    load_chunk(A, W, data, bm, bn, 0, tid);
    load_chunk(A, W, data + STG_BYTES, bm, bn, 1, tid);

    const int raL = lane & 15;
    const int akh = lane >> 4;
    const int rbL = (lane & 7) + ((lane & 16) >> 1);
    const int bkh = (lane >> 3) & 1;

    int stg_i = 0;
    for (int i = 0; i < NCHUNK; i++) {
        if (i < NCHUNK - 1)
            asm volatile("cp.async.wait_group 1;" ::: "memory");
        else
            asm volatile("cp.async.wait_group 0;" ::: "memory");
        __syncthreads();

        int nc = i + 2;
        int stg_n = stg_i + 2; if (stg_n >= NSTG) stg_n -= NSTG;
        if (nc < NCHUNK)
            load_chunk(A, W, data + stg_n * STG_BYTES, bm, bn, nc, tid);

        uint32_t sA = data + stg_i * STG_BYTES;
        uint32_t sB = sA + 16384;

#pragma unroll
        for (int ks = 0; ks < 4; ks++) {
            uint32_t a[4][4];
#pragma unroll
            for (int mt = 0; mt < 4; mt++) {
                int ra = m_base + mt * 16 + raL;
                uint32_t ck = (uint32_t)(ks * 2 + akh) ^ (uint32_t)(ra & 7);
                ldsm4(a[mt], sA + (uint32_t)(ra * 128) + (ck << 4));
            }
            uint32_t b[2][4];
#pragma unroll
            for (int nt2 = 0; nt2 < 2; nt2++) {
                int rb = n_base + nt2 * 16 + rbL;
                uint32_t ck = (uint32_t)(ks * 2 + bkh) ^ (uint32_t)(rb & 7);
                ldsm4(b[nt2], sB + (uint32_t)(rb * 128) + (ck << 4));
            }
#pragma unroll
            for (int mt = 0; mt < 4; mt++)
#pragma unroll
                for (int nt = 0; nt < 4; nt++)
                    mma16816(acc[mt][nt], a[mt], &b[nt >> 1][(nt & 1) * 2]);
        }
        if (++stg_i == NSTG) stg_i = 0;
    }
    __syncthreads();
}

// ---------------------------------------------------------------------------
// Merged QKV GEMM. grid (48, 128): wsel = x>>4, bn=(x&15)*128 (one head).
// ---------------------------------------------------------------------------
__global__ __launch_bounds__(256, 2)
void gemm_qkv(const bf16* __restrict__ A,
              const bf16* __restrict__ W0, const bf16* __restrict__ W1,
              const bf16* __restrict__ W2,
              const float* __restrict__ b0, const float* __restrict__ b1,
              const float* __restrict__ b2,
              bf16* __restrict__ qhi, bf16* __restrict__ qlo,
              bf16* __restrict__ khi, bf16* __restrict__ klo,
              bf16* __restrict__ vthi, bf16* __restrict__ vtlo) {
    extern __shared__ char dsm[];
    const uint32_t data = smem_u32(dsm);
    const int tid = threadIdx.x, wid = tid >> 5, lane = tid & 31;
    const int wsel = blockIdx.x >> 4;
    const int bn = (blockIdx.x & 15) << 7;
    const int bm = blockIdx.y << 7;
    const bf16* W = wsel == 0 ? W0 : wsel == 1 ? W1 : W2;
    const float* bias = wsel == 0 ? b0 : wsel == 1 ? b1 : b2;

    float acc[4][4][4];
#pragma unroll
    for (int mt = 0; mt < 4; mt++)
#pragma unroll
        for (int nt = 0; nt < 4; nt++)
#pragma unroll
            for (int r = 0; r < 4; r++) acc[mt][nt][r] = 0.f;

    gemm_mainloop(A, W, data, bm, bn, acc, tid, wid, lane);

    const int m_base = (wid & 1) * 64;
    const int n_base = (wid >> 1) * 32;

#pragma unroll
    for (int mt = 0; mt < 4; mt++)
#pragma unroll
        for (int nt = 0; nt < 4; nt++) {
            int col = bn + n_base + nt * 8 + (lane & 3) * 2;
            float bb0 = bias[col], bb1 = bias[col + 1];
            acc[mt][nt][0] += bb0; acc[mt][nt][1] += bb1;
            acc[mt][nt][2] += bb0; acc[mt][nt][3] += bb1;
        }

    const int b = bm >> 12, s0 = bm & 4095;
    const int page = s0 >> 8, par = (s0 >> 7) & 1;
    const int head = bn >> 7;
    size_t pb = ((size_t)((b * 16 + head) * 16 + page)) << 15;

    if (wsel < 2) {
        bf16* dhi = wsel ? khi : qhi;
        bf16* dlo = wsel ? klo : qlo;
        float* smf = (float*)dsm;  // [c:128][r:132]
#pragma unroll
        for (int mt = 0; mt < 4; mt++) {
            int r = m_base + mt * 16 + (lane >> 2);
#pragma unroll
            for (int nt = 0; nt < 4; nt++) {
                int c = n_base + nt * 8 + (lane & 3) * 2;
                smf[c * 132 + r] = acc[mt][nt][0];
                smf[(c + 1) * 132 + r] = acc[mt][nt][1];
                smf[c * 132 + r + 8] = acc[mt][nt][2];
                smf[(c + 1) * 132 + r + 8] = acc[mt][nt][3];
            }
        }
        __syncthreads();
        for (int cc = wid; cc < 128; cc += 8) {
            float4 v = *(const float4*)&smf[cc * 132 + lane * 4];
            size_t off = pb + (size_t)(par * 128 + cc) * 128 + lane * 4;
            *(uint2*)(dhi + off) = make_uint2(packhi(v.x, v.y), packhi(v.z, v.w));
            *(uint2*)(dlo + off) = make_uint2(packlo(v.x, v.y), packlo(v.z, v.w));
        }
    } else {
#pragma unroll
        for (int nt = 0; nt < 4; nt++) {
            int cw = n_base + nt * 8 + (lane & 3) * 2;
#pragma unroll
            for (int mt = 0; mt < 4; mt++) {
                int r0 = m_base + mt * 16 + (lane >> 2);
#pragma unroll
                for (int q = 0; q < 2; q++) {
                    int r = r0 + q * 8;
                    float v0 = acc[mt][nt][q * 2], v1 = acc[mt][nt][q * 2 + 1];
                    size_t off = pb + (size_t)r * 256 + par * 128 + cw;
                    *(uint32_t*)(vthi + off) = packhi(v0, v1);
                    *(uint32_t*)(vtlo + off) = packlo(v0, v1);
                }
            }
        }
    }
}

// ---------------------------------------------------------------------------
// Wo GEMM: plain fp32 output
// ---------------------------------------------------------------------------
__global__ __launch_bounds__(256, 2)
void gemm_wo(const bf16* __restrict__ A, const bf16* __restrict__ W,
             const float* __restrict__ bias, float* __restrict__ C) {
    extern __shared__ char dsm[];
    const uint32_t data = smem_u32(dsm);
    const int tid = threadIdx.x, wid = tid >> 5, lane = tid & 31;
    const int bn = blockIdx.x << 7, bm = blockIdx.y << 7;

    float acc[4][4][4];
#pragma unroll
    for (int mt = 0; mt < 4; mt++)
#pragma unroll
        for (int nt = 0; nt < 4; nt++)
#pragma unroll
            for (int r = 0; r < 4; r++) acc[mt][nt][r] = 0.f;

    gemm_mainloop(A, W, data, bm, bn, acc, tid, wid, lane);

    const int m_base = (wid & 1) * 64;
    const int n_base = (wid >> 1) * 32;
#pragma unroll
    for (int mt = 0; mt < 4; mt++) {
        int r0 = bm + m_base + mt * 16 + (lane >> 2);
#pragma unroll
        for (int nt = 0; nt < 4; nt++) {
            int col = bn + n_base + nt * 8 + (lane & 3) * 2;
            float bb0 = bias[col], bb1 = bias[col + 1];
            float* p0 = C + (size_t)r0 * NDIM + col;
            float* p1 = p0 + (size_t)8 * NDIM;
            *(float2*)p0 = make_float2(acc[mt][nt][0] + bb0, acc[mt][nt][1] + bb1);
            *(float2*)p1 = make_float2(acc[mt][nt][2] + bb0, acc[mt][nt][3] + bb1);
        }
    }
}

// ---------------------------------------------------------------------------
// attn4: FA2-style register-resident online softmax + fragment-reuse 3-term.
// 128 threads, 4 warps x 16 q-rows = 64 rows/block. 8 K/V tiles of 32.
// smem: Q 32K @0, slot0 @32K (K 16K + V 16K), slot1 @64K. 2 CTAs/SM.
// ---------------------------------------------------------------------------
#define A4_Q 0u
#define A4_S0 32768u
#define A4_S1 65536u
#define A4_SMEM 98304

__device__ __forceinline__ void a4_load_tile(
    uint32_t slot, const bf16* __restrict__ khi, const bf16* __restrict__ klo,
    const bf16* __restrict__ vthi, const bf16* __restrict__ vtlo,
    size_t pagebase, int kt, int tid) {
#pragma unroll
    for (int j = 0; j < 8; j++) {
        int idx = j * 128 + tid;
        int prec = idx >> 9, rem = idx & 511;
        int r = rem >> 4, sub = rem & 15, kc = sub >> 3, c16 = sub & 7;
        cp16(slot + prec * 8192 + kc * 4096 + swz((uint32_t)(r * 128 + c16 * 16)),
             (prec ? klo : khi) + pagebase + (size_t)(kt * 32 + r) * 128 +
                 kc * 64 + c16 * 8);
    }
#pragma unroll
    for (int j = 0; j < 8; j++) {
        int idx = j * 128 + tid;
        int prec = idx >> 9, rem = idx & 511;
        int r = rem >> 2, c16 = rem & 3;
        cp16(slot + 16384 + prec * 8192 + swz64((uint32_t)(r * 64 + c16 * 16)),
             (prec ? vtlo : vthi) + pagebase + (size_t)r * 256 + kt * 32 + c16 * 8);
    }
    CP_COMMIT();
}

__global__ __launch_bounds__(128, 2)
void attn4(const bf16* __restrict__ qhi, const bf16* __restrict__ qlo,
           const bf16* __restrict__ khi, const bf16* __restrict__ klo,
           const bf16* __restrict__ vthi, const bf16* __restrict__ vtlo,
           bf16* __restrict__ cbig) {
    extern __shared__ char smraw[];
    const uint32_t sb = smem_u32(smraw);

    const float SCALE = 0.08838834764831843f;
    const int qt = blockIdx.x, h2 = blockIdx.y, x2 = blockIdx.z;
    const int tid = threadIdx.x, wid = tid >> 5, lane = tid & 31;
    const size_t pagebase = ((size_t)(x2 * 16 + h2)) << 15;

    const int raL = lane & 15, akh = lane >> 4;
    const int rbL = (lane & 7) + ((lane & 16) >> 1), bkh = (lane >> 3) & 1;

#pragma unroll
    for (int j = 0; j < 16; j++) {
        int idx = j * 128 + tid;
        int prec = idx >> 10, rem = idx & 1023;
        int r = rem >> 4, kc = (rem >> 3) & 1, c16 = rem & 7;
        cp16(sb + A4_Q + prec * 16384 + kc * 8192 + swz((uint32_t)(r * 128 + c16 * 16)),
             (prec ? qlo : qhi) + pagebase + (size_t)(qt * 64 + r) * 128 +
                 kc * 64 + c16 * 8);
    }
    a4_load_tile(sb + A4_S0, khi, klo, vthi, vtlo, pagebase, 0, tid);
    a4_load_tile(sb + A4_S1, khi, klo, vthi, vtlo, pagebase, 1, tid);

    float out[16][4];
#pragma unroll
    for (int j = 0; j < 16; j++)
#pragma unroll
        for (int r = 0; r < 4; r++) out[j][r] = 0.f;
    float m0 = -3.4e38f, m1 = -3.4e38f, l0 = 0.f, l1 = 0.f;

#pragma unroll 1
    for (int kt = 0; kt < 8; kt++) {
        if (kt < 7) asm volatile("cp.async.wait_group 1;" ::: "memory");
        else        asm volatile("cp.async.wait_group 0;" ::: "memory");
        __syncthreads();

        uint32_t slot = sb + ((kt & 1) ? A4_S1 : A4_S0);

        // ---- S = Q K^T, fused 3-term with fragment reuse ----
        float sf[4][4];
#pragma unroll
        for (int j = 0; j < 4; j++)
#pragma unroll
            for (int r = 0; r < 4; r++) sf[j][r] = 0.f;

#pragma unroll
        for (int step = 0; step < 8; step++) {
            int kc = step >> 2, inner = step & 3;
            int ra = wid * 16 + raL;
            uint32_t ck = (uint32_t)(inner * 2 + akh) ^ (uint32_t)(ra & 7);
            uint32_t a[4], bH[2][4], bL[2][4];
            ldsm4(a, sb + A4_Q + kc * 8192 + (uint32_t)(ra * 128) + (ck << 4));
#pragma unroll
            for (int nt2 = 0; nt2 < 2; nt2++) {
                int rb = nt2 * 16 + rbL;
                uint32_t cb = (uint32_t)(inner * 2 + bkh) ^ (uint32_t)(rb & 7);
                ldsm4(bH[nt2], slot + kc * 4096 + (uint32_t)(rb * 128) + (cb << 4));
            }
#pragma unroll
            for (int nt = 0; nt < 4; nt++)
                mma16816(sf[nt], a, &bH[nt >> 1][(nt & 1) * 2]);
#pragma unroll
            for (int nt2 = 0; nt2 < 2; nt2++) {
                int rb = nt2 * 16 + rbL;
                uint32_t cb = (uint32_t)(inner * 2 + bkh) ^ (uint32_t)(rb & 7);
                ldsm4(bL[nt2], slot + 8192 + kc * 4096 + (uint32_t)(rb * 128) + (cb << 4));
            }
#pragma unroll
            for (int nt = 0; nt < 4; nt++)
                mma16816(sf[nt], a, &bL[nt >> 1][(nt & 1) * 2]);
            ldsm4(a, sb + A4_Q + 16384 + kc * 8192 + (uint32_t)(ra * 128) + (ck << 4));
#pragma unroll
            for (int nt = 0; nt < 4; nt++)
                mma16816(sf[nt], a, &bH[nt >> 1][(nt & 1) * 2]);
        }

        // ---- online softmax update ----
        float tm0 = -3.4e38f, tm1 = -3.4e38f;
#pragma unroll
        for (int j = 0; j < 4; j++) {
#pragma unroll
            for (int r = 0; r < 4; r++) sf[j][r] *= SCALE;
            tm0 = fmaxf(tm0, fmaxf(sf[j][0], sf[j][1]));
            tm1 = fmaxf(tm1, fmaxf(sf[j][2], sf[j][3]));
        }
        tm0 = fmaxf(tm0, __shfl_xor_sync(0xffffffffu, tm0, 1));
        tm0 = fmaxf(tm0, __shfl_xor_sync(0xffffffffu, tm0, 2));
        tm1 = fmaxf(tm1, __shfl_xor_sync(0xffffffffu, tm1, 1));
        tm1 = fmaxf(tm1, __shfl_xor_sync(0xffffffffu, tm1, 2));
        float mn0 = fmaxf(m0, tm0), mn1 = fmaxf(m1, tm1);
        float f0 = __expf(m0 - mn0), f1 = __expf(m1 - mn1);
        m0 = mn0; m1 = mn1;

        float ps0 = 0.f, ps1 = 0.f;
#pragma unroll
        for (int j = 0; j < 4; j++) {
            sf[j][0] = __expf(sf[j][0] - mn0);
            sf[j][1] = __expf(sf[j][1] - mn0);
            sf[j][2] = __expf(sf[j][2] - mn1);
            sf[j][3] = __expf(sf[j][3] - mn1);
            ps0 += sf[j][0] + sf[j][1];
            ps1 += sf[j][2] + sf[j][3];
        }
        ps0 += __shfl_xor_sync(0xffffffffu, ps0, 1);
        ps0 += __shfl_xor_sync(0xffffffffu, ps0, 2);
        ps1 += __shfl_xor_sync(0xffffffffu, ps1, 1);
        ps1 += __shfl_xor_sync(0xffffffffu, ps1, 2);
        l0 = l0 * f0 + ps0;
        l1 = l1 * f1 + ps1;
#pragma unroll
        for (int j = 0; j < 16; j++) {
            out[j][0] *= f0; out[j][1] *= f0;
            out[j][2] *= f1; out[j][3] *= f1;
        }

        // ---- P fragments ----
        uint32_t phi[2][4], plo[2][4];
#pragma unroll
        for (int q = 0; q < 2; q++) {
            phi[q][0] = packhi(sf[2 * q][0], sf[2 * q][1]);
            phi[q][1] = packhi(sf[2 * q][2], sf[2 * q][3]);
            phi[q][2] = packhi(sf[2 * q + 1][0], sf[2 * q + 1][1]);
            phi[q][3] = packhi(sf[2 * q + 1][2], sf[2 * q + 1][3]);
            plo[q][0] = packlo(sf[2 * q][0], sf[2 * q][1]);
            plo[q][1] = packlo(sf[2 * q][2], sf[2 * q][3]);
            plo[q][2] = packlo(sf[2 * q + 1][0], sf[2 * q + 1][1]);
            plo[q][3] = packlo(sf[2 * q + 1][2], sf[2 * q + 1][3]);
        }

        // ---- out += P V, fused 3-term with Vhi fragment reuse ----
        uint32_t Vb = slot + 16384;
#pragma unroll
        for (int ks = 0; ks < 2; ks++) {
#pragma unroll
            for (int nt2 = 0; nt2 < 8; nt2++) {
                int rb = nt2 * 16 + rbL;
                uint32_t u = (uint32_t)(ks * 2 + bkh) ^ (uint32_t)((rb & 6) >> 1);
                uint32_t bv[4];
                ldsm4(bv, Vb + (uint32_t)(rb * 64) + (u << 4));
                mma16816(out[nt2 * 2], phi[ks], &bv[0]);
                mma16816(out[nt2 * 2 + 1], phi[ks], &bv[2]);
                mma16816(out[nt2 * 2], plo[ks], &bv[0]);
                mma16816(out[nt2 * 2 + 1], plo[ks], &bv[2]);
                ldsm4(bv, Vb + 8192 + (uint32_t)(rb * 64) + (u << 4));
                mma16816(out[nt2 * 2], phi[ks], &bv[0]);
                mma16816(out[nt2 * 2 + 1], phi[ks], &bv[2]);
            }
        }
        __syncthreads();

        if (kt + 2 < 8)
            a4_load_tile(sb + ((kt & 1) ? A4_S1 : A4_S0), khi, klo, vthi, vtlo,
                         pagebase, kt + 2, tid);
    }

    // ---- epilogue ----
    const int b = x2 >> 4, head = x2 & 15;
    float il0 = 1.f / l0, il1 = 1.f / l1;
    int rg0 = qt * 64 + wid * 16 + (lane >> 2);
#pragma unroll
    for (int rr = 0; rr < 2; rr++) {
        int r = rg0 + rr * 8;
        int p2 = 2 * (r & 127) + (r >> 7);
        float il = rr ? il1 : il0;
        bf16* drow = cbig + (size_t)(b * 4096 + head * 256 + p2) * 4096;
#pragma unroll
        for (int j = 0; j < 16; j++) {
            int colb = h2 * 128 + j * 8 + (lane & 3) * 2;
            float v0 = out[j][rr * 2] * il, v1 = out[j][rr * 2 + 1] * il;
            *(uint32_t*)(drow + colb) = packhi(v0, v1);
            *(uint32_t*)(drow + 2048 + colb) = packlo(v0, v1);
        }
    }
}

// ---------------------------------------------------------------------------
extern "C" void kernel_launch(void* const* d_in, const int* in_sizes, int n_in,
                              void* d_out, int out_size) {
    const float* hidden = (const float*)d_in[0];
    const float* Wq = (const float*)d_in[1];
    const float* bq = (const float*)d_in[2];
    const float* Wk = (const float*)d_in[3];
    const float* bk = (const float*)d_in[4];
    const float* Wv = (const float*)d_in[5];
    const float* bv = (const float*)d_in[6];
    const float* Wo = (const float*)d_in[7];
    const float* bo = (const float*)d_in[8];
    float* out = (float*)d_out;

    bf16 *hbig, *cbig, *wq, *wk, *wv, *wo;
    bf16 *qhi, *qlo, *khi, *klo, *vthi, *vtlo;
    cudaGetSymbolAddress((void**)&hbig, g_hbig);
    cudaGetSymbolAddress((void**)&cbig, g_cbig);
    cudaGetSymbolAddress((void**)&wq, g_wq);
    cudaGetSymbolAddress((void**)&wk, g_wk);
    cudaGetSymbolAddress((void**)&wv, g_wv);
    cudaGetSymbolAddress((void**)&wo, g_wo);
    cudaGetSymbolAddress((void**)&qhi, g_qhi);
    cudaGetSymbolAddress((void**)&qlo, g_qlo);
    cudaGetSymbolAddress((void**)&khi, g_khi);
    cudaGetSymbolAddress((void**)&klo, g_klo);
    cudaGetSymbolAddress((void**)&vthi, g_vthi);
    cudaGetSymbolAddress((void**)&vtlo, g_vtlo);

    cudaFuncSetAttribute(gemm_qkv, cudaFuncAttributeMaxDynamicSharedMemorySize,
                         GEMM_SMEM);
    cudaFuncSetAttribute(gemm_wo, cudaFuncAttributeMaxDynamicSharedMemorySize,
                         GEMM_SMEM);
    cudaFuncSetAttribute(attn4, cudaFuncAttributeMaxDynamicSharedMemorySize,
                         A4_SMEM);

    make_split4<<<dim3(4096, 4), 256>>>(Wq, wq, Wk, wk, Wv, wv, Wo, wo);
    make_split<<<32768, 256>>>(hidden, hbig);

    gemm_qkv<<<dim3(48, 128), 256, GEMM_SMEM>>>(
        hbig, wq, wk, wv, bq, bk, bv, qhi, qlo, khi, klo, vthi, vtlo);
    attn4<<<dim3(4, 16, 64), 128, A4_SMEM>>>(qhi, qlo, khi, klo, vthi, vtlo, cbig);
    gemm_wo<<<dim3(16, 128), 256, GEMM_SMEM>>>(cbig, wo, bo, out);
}